// round 1
// baseline (speedup 1.0000x reference)
#include <cuda_runtime.h>
#include <cuda_bf16.h>

#define BB   8
#define TLEN 32000
#define RES  64
#define GATE 128
#define SKC  64
#define CINC 80
#define NL   30
#define OUTC 256
#define TILE 128
#define NTH  256

#define SMEM_LAYER ((RES*TILE*2 + CINC*TILE) * 4)   /* 106496 bytes */
#define SMEM_FINAL (RES*TILE*2 * 4)                 /* 65536 bytes  */

// ---------------- device scratch (no allocations allowed) ----------------
__device__ float g_hA[BB*RES*TLEN];
__device__ float g_hB[BB*RES*TLEN];
__device__ float g_skip[BB*SKC*TLEN];
__device__ float g_c[BB*CINC*TLEN];
__device__ float g_cA[BB*CINC*400];
__device__ float g_cB[BB*CINC*4000];
__device__ float g_Wg[NL*208*GATE];
__device__ float g_Wz[NL*64*GATE];
__device__ int   g_xflag;   // 1 => x stored as int32, 0 => int64

// ---------------- helpers ----------------
__device__ __forceinline__ float sigf(float x) {
    return __fdividef(1.f, 1.f + __expf(-x));
}
__device__ __forceinline__ float tanhfast(float x) {
    return 2.f * sigf(2.f * x) - 1.f;
}

// ---------------- dtype detection for x ----------------
__global__ void k_detect(const unsigned* __restrict__ xu) {
    __shared__ int s_any;
    if (threadIdx.x == 0) s_any = 0;
    __syncthreads();
    int any = 0;
    // If x is int64 (values < 256), every odd 32-bit word is the zero high word.
    // If x is int32, odd words are random samples in [0,256) -> some nonzero.
    for (int i = 1 + 2*threadIdx.x; i < BB*TLEN; i += 2*blockDim.x)
        any |= (xu[i] != 0u);
    if (any) atomicOr(&s_any, 1);
    __syncthreads();
    if (threadIdx.x == 0) g_xflag = s_any;
}

// ---------------- first 1x1 conv (one-hot gather) + skip reset ----------------
__global__ void k_first(const void* __restrict__ xraw,
                        const float* __restrict__ fw,
                        const float* __restrict__ fb) {
    int g = blockIdx.x * blockDim.x + threadIdx.x;
    if (g >= BB*TLEN) return;
    int t = g % TLEN, b = g / TLEN;
    int xi = g_xflag ? ((const int*)xraw)[g]
                     : (int)(((const long long*)xraw)[g]);
    #pragma unroll 4
    for (int o = 0; o < RES; ++o) {
        g_hA[(b*RES + o)*TLEN + t]  = fw[o*OUTC + xi] + fb[o];
        g_skip[(b*SKC + o)*TLEN + t] = 0.f;
    }
}

// ---------------- weight packing (k-major) ----------------
__global__ void k_prep(const float* __restrict__ conv_w,
                       const float* __restrict__ cond_w,
                       const float* __restrict__ skip_w,
                       const float* __restrict__ out_w) {
    int i = blockIdx.x * blockDim.x + threadIdx.x;
    const int NG = NL*208*GATE;
    if (i < NG) {
        int l = i / (208*GATE);
        int rem = i % (208*GATE);
        int r = rem / GATE, o = rem % GATE;
        float v;
        if (r < 64)        v = conv_w[((l*GATE + o)*RES + r)*2 + 0];
        else if (r < 128)  v = conv_w[((l*GATE + o)*RES + (r-64))*2 + 1];
        else               v = cond_w[(l*GATE + o)*CINC + (r-128)];
        g_Wg[i] = v;
    } else {
        int j = i - NG;
        if (j < NL*64*GATE) {
            int l = j / (64*GATE);
            int rem = j % (64*GATE);
            int k = rem / GATE, o = rem % GATE;
            g_Wz[j] = (o < 64) ? skip_w[(l*SKC + o)*64 + k]
                               : out_w[(l*RES + (o-64))*64 + k];
        }
    }
}

// ---------------- conditioning upsample ----------------
__global__ void k_upA(const float* __restrict__ cond,
                      const float* __restrict__ cin_w) {
    int i = blockIdx.x * blockDim.x + threadIdx.x;
    if (i >= BB*CINC*400) return;
    int f = i % 400, o = (i/400) % CINC, b = i / (CINC*400);
    const float* cp = cond + b*CINC*400 + f;
    const float* wp = cin_w + o*CINC;
    float s = 0.f;
    #pragma unroll 8
    for (int k = 0; k < CINC; ++k) s += wp[k] * cp[k*400];
    g_cA[i] = s;
}

__global__ void k_upB() {
    int i = blockIdx.x * blockDim.x + threadIdx.x;
    if (i >= BB*CINC*4000) return;
    int t = i % 4000, bc = i / 4000;
    int lo = (t-10 < 0) ? 0 : t-10;
    int hi = (t+10 > 3999) ? 3999 : t+10;
    const float* src = g_cA + bc*400;
    float s = 0.f;
    for (int j = lo; j <= hi; ++j) s += src[j/10];
    g_cB[i] = s * (1.f/21.f);
}

__global__ void k_upC() {
    int i = blockIdx.x * blockDim.x + threadIdx.x;
    if (i >= BB*CINC*TLEN) return;
    int t = i % TLEN, bc = i / TLEN;
    int lo = (t-8 < 0) ? 0 : t-8;
    int hi = (t+8 > TLEN-1) ? TLEN-1 : t+8;
    const float* src = g_cB + bc*4000;
    float s = 0.f;
    for (int j = lo; j <= hi; ++j) s += src[j >> 3];
    g_c[i] = s * (1.f/17.f);
}

// ---------------- per-layer fused kernel ----------------
// Per thread: 4 output channels x 16 timesteps (t = tg + 8*j interleave).
__device__ __forceinline__ void gemm_acc(const float* __restrict__ W,
                                         const float* __restrict__ S,
                                         int rows, int og, int tg,
                                         float acc[4][16]) {
    #pragma unroll 4
    for (int r = 0; r < rows; ++r) {
        float4 w = *(const float4*)(W + r*GATE + og*4);
        const float* sv = S + r*TILE + tg;
        #pragma unroll
        for (int j = 0; j < 16; ++j) {
            float h = sv[j*8];
            acc[0][j] = fmaf(w.x, h, acc[0][j]);
            acc[1][j] = fmaf(w.y, h, acc[1][j]);
            acc[2][j] = fmaf(w.z, h, acc[2][j]);
            acc[3][j] = fmaf(w.w, h, acc[3][j]);
        }
    }
}

__global__ void __launch_bounds__(NTH, 2) k_layer(int l, int d,
        const float* __restrict__ conv_b,
        const float* __restrict__ skip_b,
        const float* __restrict__ out_b) {
    extern __shared__ float sm[];
    float* sh_hc = sm;                   // [64][128]
    float* sh_hp = sm + RES*TILE;        // [64][128]
    float* sh_c  = sm + 2*RES*TILE;      // [80][128]
    float* sh_g  = sm + RES*TILE;        // [128][128], overlaps hp+c after sync

    const float* hin  = (l & 1) ? g_hB : g_hA;
    float*       hout = (l & 1) ? g_hA : g_hB;

    int b  = blockIdx.y;
    int t0 = blockIdx.x * TILE;
    int tid = threadIdx.x;
    const float* hb = hin + b*RES*TLEN;

    // load h(t) tile (vectorized)
    for (int i = tid; i < RES*(TILE/4); i += NTH) {
        int r = i >> 5, c4 = i & 31;
        ((float4*)sh_hc)[i] = *(const float4*)(hb + r*TLEN + t0 + c4*4);
    }
    // load h(t-d) tile with zero pad
    for (int i = tid; i < RES*TILE; i += NTH) {
        int r = i >> 7, c = i & (TILE-1);
        int t = t0 - d + c;
        sh_hp[i] = (t >= 0) ? hb[r*TLEN + t] : 0.f;
    }
    // load c tile
    const float* cb = g_c + b*CINC*TLEN;
    for (int i = tid; i < CINC*(TILE/4); i += NTH) {
        int r = i >> 5, c4 = i & 31;
        ((float4*)sh_c)[i] = *(const float4*)(cb + r*TLEN + t0 + c4*4);
    }
    __syncthreads();

    int og = tid >> 3;   // 0..31 -> output channels og*4..og*4+3
    int tg = tid & 7;    // timestep phase

    // --- stage 1: g = W0 @ h(t-d) + W1 @ h(t) + Wc @ c + bias ---
    float acc[4][16];
    {
        float b0 = conv_b[og*4+0], b1 = conv_b[og*4+1];
        float b2 = conv_b[og*4+2], b3 = conv_b[og*4+3];
        #pragma unroll
        for (int j = 0; j < 16; ++j) {
            acc[0][j] = b0; acc[1][j] = b1; acc[2][j] = b2; acc[3][j] = b3;
        }
    }
    const float* Wl = g_Wg + (size_t)l*208*GATE;
    gemm_acc(Wl,            sh_hp, 64, og, tg, acc);
    gemm_acc(Wl + 64*GATE,  sh_hc, 64, og, tg, acc);
    gemm_acc(Wl + 128*GATE, sh_c,  80, og, tg, acc);
    __syncthreads();   // done reading hp/c; reuse region for g

    #pragma unroll
    for (int i = 0; i < 4; ++i)
        #pragma unroll
        for (int j = 0; j < 16; ++j)
            sh_g[(og*4 + i)*TILE + tg + 8*j] = acc[i][j];
    __syncthreads();

    // --- gate: z = tanh(a) * sigmoid(b), in place over rows 0..63 ---
    for (int i = tid; i < 64*TILE; i += NTH) {
        float a  = sh_g[i];
        float bq = sh_g[i + 64*TILE];
        sh_g[i] = tanhfast(a) * sigf(bq);
    }
    __syncthreads();

    // --- stage 2: [skip_w; out_w] @ z ---
    float acc2[4][16];
    {
        const float* bias = (og < 16) ? (skip_b + og*4) : (out_b + (og-16)*4);
        float b0 = bias[0], b1 = bias[1], b2 = bias[2], b3 = bias[3];
        #pragma unroll
        for (int j = 0; j < 16; ++j) {
            acc2[0][j] = b0; acc2[1][j] = b1; acc2[2][j] = b2; acc2[3][j] = b3;
        }
    }
    gemm_acc(g_Wz + (size_t)l*64*GATE, sh_g, 64, og, tg, acc2);

    if (og < 16) {
        float* sp = g_skip + (b*SKC + og*4)*TLEN + t0 + tg;
        #pragma unroll
        for (int i = 0; i < 4; ++i)
            #pragma unroll
            for (int j = 0; j < 16; ++j)
                sp[i*TLEN + 8*j] += acc2[i][j];
    } else {
        int oo = (og - 16) * 4;
        float* hp = hout + (b*RES + oo)*TLEN + t0 + tg;
        const float* hcv = sh_hc + oo*TILE + tg;
        #pragma unroll
        for (int i = 0; i < 4; ++i)
            #pragma unroll
            for (int j = 0; j < 16; ++j)
                hp[i*TLEN + 8*j] = hcv[i*TILE + 8*j] + acc2[i][j];
    }
}

// ---------------- output head: relu -> 64x64 -> relu -> 256x64 ----------------
__global__ void __launch_bounds__(NTH) k_final(const float* __restrict__ w1,
                                               const float* __restrict__ b1,
                                               const float* __restrict__ w2,
                                               const float* __restrict__ b2,
                                               float* __restrict__ out) {
    extern __shared__ float sm[];
    float* sh_s = sm;              // relu(skips) [64][128]
    float* sh_y = sm + RES*TILE;   // relu(y1)    [64][128]
    int b = blockIdx.y, t0 = blockIdx.x * TILE, tid = threadIdx.x;

    for (int i = tid; i < RES*(TILE/4); i += NTH) {
        int r = i >> 5, c4 = i & 31;
        float4 v = *(const float4*)(g_skip + (b*SKC + r)*TLEN + t0 + c4*4);
        v.x = fmaxf(v.x, 0.f); v.y = fmaxf(v.y, 0.f);
        v.z = fmaxf(v.z, 0.f); v.w = fmaxf(v.w, 0.f);
        ((float4*)sh_s)[i] = v;
    }
    __syncthreads();

    int og = tid >> 3, tg = tid & 7;   // og 0..31

    // phase A: y1 = relu(w1 @ s + b1), 2 channels per thread
    {
        float a0[16], a1[16];
        float c0 = b1[og*2], c1 = b1[og*2+1];
        #pragma unroll
        for (int j = 0; j < 16; ++j) { a0[j] = c0; a1[j] = c1; }
        #pragma unroll 4
        for (int r = 0; r < 64; ++r) {
            float w0 = w1[(og*2+0)*64 + r];
            float w1v = w1[(og*2+1)*64 + r];
            const float* sv = sh_s + r*TILE + tg;
            #pragma unroll
            for (int j = 0; j < 16; ++j) {
                float s = sv[8*j];
                a0[j] = fmaf(w0,  s, a0[j]);
                a1[j] = fmaf(w1v, s, a1[j]);
            }
        }
        #pragma unroll
        for (int j = 0; j < 16; ++j) {
            sh_y[(og*2+0)*TILE + tg + 8*j] = fmaxf(a0[j], 0.f);
            sh_y[(og*2+1)*TILE + tg + 8*j] = fmaxf(a1[j], 0.f);
        }
    }
    __syncthreads();

    // phase B: y = w2 @ y1 + b2, 256 channels in two passes of 4/thread
    #pragma unroll 1
    for (int p = 0; p < 2; ++p) {
        int ob = p*128 + og*4;
        float acc[4][16];
        {
            float c0 = b2[ob+0], c1 = b2[ob+1], c2 = b2[ob+2], c3 = b2[ob+3];
            #pragma unroll
            for (int j = 0; j < 16; ++j) {
                acc[0][j] = c0; acc[1][j] = c1; acc[2][j] = c2; acc[3][j] = c3;
            }
        }
        #pragma unroll 4
        for (int r = 0; r < 64; ++r) {
            float w0 = w2[(ob+0)*64 + r];
            float w1v = w2[(ob+1)*64 + r];
            float w2v = w2[(ob+2)*64 + r];
            float w3v = w2[(ob+3)*64 + r];
            const float* yv = sh_y + r*TILE + tg;
            #pragma unroll
            for (int j = 0; j < 16; ++j) {
                float y = yv[8*j];
                acc[0][j] = fmaf(w0,  y, acc[0][j]);
                acc[1][j] = fmaf(w1v, y, acc[1][j]);
                acc[2][j] = fmaf(w2v, y, acc[2][j]);
                acc[3][j] = fmaf(w3v, y, acc[3][j]);
            }
        }
        float* op = out + ((size_t)b*OUTC + ob)*TLEN + t0 + tg;
        #pragma unroll
        for (int i = 0; i < 4; ++i)
            #pragma unroll
            for (int j = 0; j < 16; ++j)
                op[(size_t)i*TLEN + 8*j] = acc[i][j];
    }
}

// ---------------- launch ----------------
extern "C" void kernel_launch(void* const* d_in, const int* in_sizes, int n_in,
                              void* d_out, int out_size) {
    (void)in_sizes; (void)n_in; (void)out_size;
    const void*  x       = d_in[0];
    const float* cond    = (const float*)d_in[1];
    const float* first_w = (const float*)d_in[2];
    const float* first_b = (const float*)d_in[3];
    const float* cin_w   = (const float*)d_in[4];
    const float* conv_w  = (const float*)d_in[5];
    const float* conv_b  = (const float*)d_in[6];
    const float* cond_w  = (const float*)d_in[7];
    const float* skip_w  = (const float*)d_in[8];
    const float* skip_b  = (const float*)d_in[9];
    const float* out_w   = (const float*)d_in[10];
    const float* out_b   = (const float*)d_in[11];
    const float* l1w     = (const float*)d_in[12];
    const float* l1b     = (const float*)d_in[13];
    const float* l2w     = (const float*)d_in[14];
    const float* l2b     = (const float*)d_in[15];
    float* out = (float*)d_out;

    cudaFuncSetAttribute(k_layer, cudaFuncAttributeMaxDynamicSharedMemorySize, SMEM_LAYER);
    cudaFuncSetAttribute(k_final, cudaFuncAttributeMaxDynamicSharedMemorySize, SMEM_FINAL);

    k_detect<<<1, 256>>>((const unsigned*)x);
    k_first<<<(BB*TLEN + 255)/256, 256>>>(x, first_w, first_b);

    int nprep = NL*208*GATE + NL*64*GATE;
    k_prep<<<(nprep + 255)/256, 256>>>(conv_w, cond_w, skip_w, out_w);

    k_upA<<<(BB*CINC*400  + 255)/256, 256>>>(cond, cin_w);
    k_upB<<<(BB*CINC*4000 + 255)/256, 256>>>();
    k_upC<<<(BB*CINC*TLEN + 255)/256, 256>>>();

    dim3 grid(TLEN/TILE, BB);
    for (int l = 0; l < NL; ++l) {
        int d = 1 << (l % 10);
        k_layer<<<grid, NTH, SMEM_LAYER>>>(l, d,
            conv_b + l*GATE, skip_b + l*SKC, out_b + l*RES);
    }
    k_final<<<grid, NTH, SMEM_FINAL>>>(l1w, l1b, l2w, l2b, out);
}

// round 2
// speedup vs baseline: 1.0000x; 1.0000x over previous
#include <cuda_runtime.h>
#include <cuda_bf16.h>

#define BB   8
#define TLEN 32000
#define RES  64
#define GATE 128
#define SKC  64
#define CINC 80
#define NL   30
#define OUTC 256
#define TILE 128
#define NTH  256

#define SMEM_LAYER ((RES*TILE*2 + CINC*TILE) * 4)   /* 106496 bytes */
#define SMEM_FINAL (RES*TILE*2 * 4)                 /* 65536 bytes  */

// ---------------- device scratch (no allocations allowed) ----------------
__device__ float g_hA[BB*RES*TLEN];
__device__ float g_hB[BB*RES*TLEN];
__device__ float g_skip[BB*SKC*TLEN];
__device__ float g_c[BB*CINC*TLEN];
__device__ float g_cA[BB*CINC*400];
__device__ float g_cB[BB*CINC*4000];
__device__ float g_Wg[NL*208*GATE];
__device__ float g_Wz[NL*64*GATE];
__device__ int   g_xflag;   // 1 => x stored as int32, 0 => int64

// ---------------- helpers ----------------
__device__ __forceinline__ float sigf(float x) {
    return __fdividef(1.f, 1.f + __expf(-x));
}
__device__ __forceinline__ float tanhfast(float x) {
    return 2.f * sigf(2.f * x) - 1.f;
}

// ---------------- dtype detection for x ----------------
__global__ void k_detect(const unsigned* __restrict__ xu) {
    __shared__ int s_any;
    if (threadIdx.x == 0) s_any = 0;
    __syncthreads();
    int any = 0;
    // If x is int64 (values < 256), every odd 32-bit word is the zero high word.
    // If x is int32, odd words are random samples in [0,256) -> some nonzero.
    for (int i = 1 + 2*threadIdx.x; i < BB*TLEN; i += 2*blockDim.x)
        any |= (xu[i] != 0u);
    if (any) atomicOr(&s_any, 1);
    __syncthreads();
    if (threadIdx.x == 0) g_xflag = s_any;
}

// ---------------- first 1x1 conv (one-hot gather) + skip reset ----------------
__global__ void k_first(const void* __restrict__ xraw,
                        const float* __restrict__ fw,
                        const float* __restrict__ fb) {
    int g = blockIdx.x * blockDim.x + threadIdx.x;
    if (g >= BB*TLEN) return;
    int t = g % TLEN, b = g / TLEN;
    int xi = g_xflag ? ((const int*)xraw)[g]
                     : (int)(((const long long*)xraw)[g]);
    #pragma unroll 4
    for (int o = 0; o < RES; ++o) {
        g_hA[(b*RES + o)*TLEN + t]  = fw[o*OUTC + xi] + fb[o];
        g_skip[(b*SKC + o)*TLEN + t] = 0.f;
    }
}

// ---------------- weight packing (k-major) ----------------
__global__ void k_prep(const float* __restrict__ conv_w,
                       const float* __restrict__ cond_w,
                       const float* __restrict__ skip_w,
                       const float* __restrict__ out_w) {
    int i = blockIdx.x * blockDim.x + threadIdx.x;
    const int NG = NL*208*GATE;
    if (i < NG) {
        int l = i / (208*GATE);
        int rem = i % (208*GATE);
        int r = rem / GATE, o = rem % GATE;
        float v;
        if (r < 64)        v = conv_w[((l*GATE + o)*RES + r)*2 + 0];
        else if (r < 128)  v = conv_w[((l*GATE + o)*RES + (r-64))*2 + 1];
        else               v = cond_w[(l*GATE + o)*CINC + (r-128)];
        g_Wg[i] = v;
    } else {
        int j = i - NG;
        if (j < NL*64*GATE) {
            int l = j / (64*GATE);
            int rem = j % (64*GATE);
            int k = rem / GATE, o = rem % GATE;
            g_Wz[j] = (o < 64) ? skip_w[(l*SKC + o)*64 + k]
                               : out_w[(l*RES + (o-64))*64 + k];
        }
    }
}

// ---------------- conditioning upsample ----------------
__global__ void k_upA(const float* __restrict__ cond,
                      const float* __restrict__ cin_w) {
    int i = blockIdx.x * blockDim.x + threadIdx.x;
    if (i >= BB*CINC*400) return;
    int f = i % 400, o = (i/400) % CINC, b = i / (CINC*400);
    const float* cp = cond + b*CINC*400 + f;
    const float* wp = cin_w + o*CINC;
    float s = 0.f;
    #pragma unroll 8
    for (int k = 0; k < CINC; ++k) s += wp[k] * cp[k*400];
    g_cA[i] = s;
}

__global__ void k_upB() {
    int i = blockIdx.x * blockDim.x + threadIdx.x;
    if (i >= BB*CINC*4000) return;
    int t = i % 4000, bc = i / 4000;
    int lo = (t-10 < 0) ? 0 : t-10;
    int hi = (t+10 > 3999) ? 3999 : t+10;
    const float* src = g_cA + bc*400;
    float s = 0.f;
    for (int j = lo; j <= hi; ++j) s += src[j/10];
    g_cB[i] = s * (1.f/21.f);
}

__global__ void k_upC() {
    int i = blockIdx.x * blockDim.x + threadIdx.x;
    if (i >= BB*CINC*TLEN) return;
    int t = i % TLEN, bc = i / TLEN;
    int lo = (t-8 < 0) ? 0 : t-8;
    int hi = (t+8 > TLEN-1) ? TLEN-1 : t+8;
    const float* src = g_cB + bc*4000;
    float s = 0.f;
    for (int j = lo; j <= hi; ++j) s += src[j >> 3];
    g_c[i] = s * (1.f/17.f);
}

// ---------------- per-layer fused kernel ----------------
// Per thread: 4 output channels x 16 timesteps (t = tg + 8*j interleave).
__device__ __forceinline__ void gemm_acc(const float* __restrict__ W,
                                         const float* __restrict__ S,
                                         int rows, int og, int tg,
                                         float acc[4][16]) {
    #pragma unroll 4
    for (int r = 0; r < rows; ++r) {
        float4 w = *(const float4*)(W + r*GATE + og*4);
        const float* sv = S + r*TILE + tg;
        #pragma unroll
        for (int j = 0; j < 16; ++j) {
            float h = sv[j*8];
            acc[0][j] = fmaf(w.x, h, acc[0][j]);
            acc[1][j] = fmaf(w.y, h, acc[1][j]);
            acc[2][j] = fmaf(w.z, h, acc[2][j]);
            acc[3][j] = fmaf(w.w, h, acc[3][j]);
        }
    }
}

__global__ void __launch_bounds__(NTH, 2) k_layer(int l, int d,
        const float* __restrict__ conv_b,
        const float* __restrict__ skip_b,
        const float* __restrict__ out_b) {
    extern __shared__ float sm[];
    float* sh_hc = sm;                   // [64][128]
    float* sh_hp = sm + RES*TILE;        // [64][128]
    float* sh_c  = sm + 2*RES*TILE;      // [80][128]
    float* sh_g  = sm + RES*TILE;        // [128][128], overlaps hp+c after sync

    const float* hin  = (l & 1) ? g_hB : g_hA;
    float*       hout = (l & 1) ? g_hA : g_hB;

    int b  = blockIdx.y;
    int t0 = blockIdx.x * TILE;
    int tid = threadIdx.x;
    const float* hb = hin + b*RES*TLEN;

    // load h(t) tile (vectorized)
    for (int i = tid; i < RES*(TILE/4); i += NTH) {
        int r = i >> 5, c4 = i & 31;
        ((float4*)sh_hc)[i] = *(const float4*)(hb + r*TLEN + t0 + c4*4);
    }
    // load h(t-d) tile with zero pad
    for (int i = tid; i < RES*TILE; i += NTH) {
        int r = i >> 7, c = i & (TILE-1);
        int t = t0 - d + c;
        sh_hp[i] = (t >= 0) ? hb[r*TLEN + t] : 0.f;
    }
    // load c tile
    const float* cb = g_c + b*CINC*TLEN;
    for (int i = tid; i < CINC*(TILE/4); i += NTH) {
        int r = i >> 5, c4 = i & 31;
        ((float4*)sh_c)[i] = *(const float4*)(cb + r*TLEN + t0 + c4*4);
    }
    __syncthreads();

    int og = tid >> 3;   // 0..31 -> output channels og*4..og*4+3
    int tg = tid & 7;    // timestep phase

    // --- stage 1: g = W0 @ h(t-d) + W1 @ h(t) + Wc @ c + bias ---
    float acc[4][16];
    {
        float b0 = conv_b[og*4+0], b1 = conv_b[og*4+1];
        float b2 = conv_b[og*4+2], b3 = conv_b[og*4+3];
        #pragma unroll
        for (int j = 0; j < 16; ++j) {
            acc[0][j] = b0; acc[1][j] = b1; acc[2][j] = b2; acc[3][j] = b3;
        }
    }
    const float* Wl = g_Wg + (size_t)l*208*GATE;
    gemm_acc(Wl,            sh_hp, 64, og, tg, acc);
    gemm_acc(Wl + 64*GATE,  sh_hc, 64, og, tg, acc);
    gemm_acc(Wl + 128*GATE, sh_c,  80, og, tg, acc);
    __syncthreads();   // done reading hp/c; reuse region for g

    #pragma unroll
    for (int i = 0; i < 4; ++i)
        #pragma unroll
        for (int j = 0; j < 16; ++j)
            sh_g[(og*4 + i)*TILE + tg + 8*j] = acc[i][j];
    __syncthreads();

    // --- gate: z = tanh(a) * sigmoid(b), in place over rows 0..63 ---
    for (int i = tid; i < 64*TILE; i += NTH) {
        float a  = sh_g[i];
        float bq = sh_g[i + 64*TILE];
        sh_g[i] = tanhfast(a) * sigf(bq);
    }
    __syncthreads();

    // --- stage 2: [skip_w; out_w] @ z ---
    float acc2[4][16];
    {
        const float* bias = (og < 16) ? (skip_b + og*4) : (out_b + (og-16)*4);
        float b0 = bias[0], b1 = bias[1], b2 = bias[2], b3 = bias[3];
        #pragma unroll
        for (int j = 0; j < 16; ++j) {
            acc2[0][j] = b0; acc2[1][j] = b1; acc2[2][j] = b2; acc2[3][j] = b3;
        }
    }
    gemm_acc(g_Wz + (size_t)l*64*GATE, sh_g, 64, og, tg, acc2);

    if (og < 16) {
        float* sp = g_skip + (b*SKC + og*4)*TLEN + t0 + tg;
        #pragma unroll
        for (int i = 0; i < 4; ++i)
            #pragma unroll
            for (int j = 0; j < 16; ++j)
                sp[i*TLEN + 8*j] += acc2[i][j];
    } else {
        int oo = (og - 16) * 4;
        float* hp = hout + (b*RES + oo)*TLEN + t0 + tg;
        const float* hcv = sh_hc + oo*TILE + tg;
        #pragma unroll
        for (int i = 0; i < 4; ++i)
            #pragma unroll
            for (int j = 0; j < 16; ++j)
                hp[i*TLEN + 8*j] = hcv[i*TILE + 8*j] + acc2[i][j];
    }
}

// ---------------- output head: relu -> 64x64 -> relu -> 256x64 ----------------
__global__ void __launch_bounds__(NTH) k_final(const float* __restrict__ w1,
                                               const float* __restrict__ b1,
                                               const float* __restrict__ w2,
                                               const float* __restrict__ b2,
                                               float* __restrict__ out) {
    extern __shared__ float sm[];
    float* sh_s = sm;              // relu(skips) [64][128]
    float* sh_y = sm + RES*TILE;   // relu(y1)    [64][128]
    int b = blockIdx.y, t0 = blockIdx.x * TILE, tid = threadIdx.x;

    for (int i = tid; i < RES*(TILE/4); i += NTH) {
        int r = i >> 5, c4 = i & 31;
        float4 v = *(const float4*)(g_skip + (b*SKC + r)*TLEN + t0 + c4*4);
        v.x = fmaxf(v.x, 0.f); v.y = fmaxf(v.y, 0.f);
        v.z = fmaxf(v.z, 0.f); v.w = fmaxf(v.w, 0.f);
        ((float4*)sh_s)[i] = v;
    }
    __syncthreads();

    int og = tid >> 3, tg = tid & 7;   // og 0..31

    // phase A: y1 = relu(w1 @ s + b1), 2 channels per thread
    {
        float a0[16], a1[16];
        float c0 = b1[og*2], c1 = b1[og*2+1];
        #pragma unroll
        for (int j = 0; j < 16; ++j) { a0[j] = c0; a1[j] = c1; }
        #pragma unroll 4
        for (int r = 0; r < 64; ++r) {
            float w0 = w1[(og*2+0)*64 + r];
            float w1v = w1[(og*2+1)*64 + r];
            const float* sv = sh_s + r*TILE + tg;
            #pragma unroll
            for (int j = 0; j < 16; ++j) {
                float s = sv[8*j];
                a0[j] = fmaf(w0,  s, a0[j]);
                a1[j] = fmaf(w1v, s, a1[j]);
            }
        }
        #pragma unroll
        for (int j = 0; j < 16; ++j) {
            sh_y[(og*2+0)*TILE + tg + 8*j] = fmaxf(a0[j], 0.f);
            sh_y[(og*2+1)*TILE + tg + 8*j] = fmaxf(a1[j], 0.f);
        }
    }
    __syncthreads();

    // phase B: y = w2 @ y1 + b2, 256 channels in two passes of 4/thread
    #pragma unroll 1
    for (int p = 0; p < 2; ++p) {
        int ob = p*128 + og*4;
        float acc[4][16];
        {
            float c0 = b2[ob+0], c1 = b2[ob+1], c2 = b2[ob+2], c3 = b2[ob+3];
            #pragma unroll
            for (int j = 0; j < 16; ++j) {
                acc[0][j] = c0; acc[1][j] = c1; acc[2][j] = c2; acc[3][j] = c3;
            }
        }
        #pragma unroll 4
        for (int r = 0; r < 64; ++r) {
            float w0 = w2[(ob+0)*64 + r];
            float w1v = w2[(ob+1)*64 + r];
            float w2v = w2[(ob+2)*64 + r];
            float w3v = w2[(ob+3)*64 + r];
            const float* yv = sh_y + r*TILE + tg;
            #pragma unroll
            for (int j = 0; j < 16; ++j) {
                float y = yv[8*j];
                acc[0][j] = fmaf(w0,  y, acc[0][j]);
                acc[1][j] = fmaf(w1v, y, acc[1][j]);
                acc[2][j] = fmaf(w2v, y, acc[2][j]);
                acc[3][j] = fmaf(w3v, y, acc[3][j]);
            }
        }
        float* op = out + ((size_t)b*OUTC + ob)*TLEN + t0 + tg;
        #pragma unroll
        for (int i = 0; i < 4; ++i)
            #pragma unroll
            for (int j = 0; j < 16; ++j)
                op[(size_t)i*TLEN + 8*j] = acc[i][j];
    }
}

// ---------------- launch ----------------
extern "C" void kernel_launch(void* const* d_in, const int* in_sizes, int n_in,
                              void* d_out, int out_size) {
    (void)in_sizes; (void)n_in; (void)out_size;
    const void*  x       = d_in[0];
    const float* cond    = (const float*)d_in[1];
    const float* first_w = (const float*)d_in[2];
    const float* first_b = (const float*)d_in[3];
    const float* cin_w   = (const float*)d_in[4];
    const float* conv_w  = (const float*)d_in[5];
    const float* conv_b  = (const float*)d_in[6];
    const float* cond_w  = (const float*)d_in[7];
    const float* skip_w  = (const float*)d_in[8];
    const float* skip_b  = (const float*)d_in[9];
    const float* out_w   = (const float*)d_in[10];
    const float* out_b   = (const float*)d_in[11];
    const float* l1w     = (const float*)d_in[12];
    const float* l1b     = (const float*)d_in[13];
    const float* l2w     = (const float*)d_in[14];
    const float* l2b     = (const float*)d_in[15];
    float* out = (float*)d_out;

    cudaFuncSetAttribute(k_layer, cudaFuncAttributeMaxDynamicSharedMemorySize, SMEM_LAYER);
    cudaFuncSetAttribute(k_final, cudaFuncAttributeMaxDynamicSharedMemorySize, SMEM_FINAL);

    k_detect<<<1, 256>>>((const unsigned*)x);
    k_first<<<(BB*TLEN + 255)/256, 256>>>(x, first_w, first_b);

    int nprep = NL*208*GATE + NL*64*GATE;
    k_prep<<<(nprep + 255)/256, 256>>>(conv_w, cond_w, skip_w, out_w);

    k_upA<<<(BB*CINC*400  + 255)/256, 256>>>(cond, cin_w);
    k_upB<<<(BB*CINC*4000 + 255)/256, 256>>>();
    k_upC<<<(BB*CINC*TLEN + 255)/256, 256>>>();

    dim3 grid(TLEN/TILE, BB);
    for (int l = 0; l < NL; ++l) {
        int d = 1 << (l % 10);
        k_layer<<<grid, NTH, SMEM_LAYER>>>(l, d,
            conv_b + l*GATE, skip_b + l*SKC, out_b + l*RES);
    }
    k_final<<<grid, NTH, SMEM_FINAL>>>(l1w, l1b, l2w, l2b, out);
}

// round 3
// speedup vs baseline: 1.2104x; 1.2104x over previous
#include <cuda_runtime.h>
#include <cuda_bf16.h>

#define BB   8
#define TLEN 32000
#define RES  64
#define GATE 128
#define SKC  64
#define CINC 80
#define NL   30
#define OUTC 256
#define TILE 128
#define NTH  256

#define SMEM_LAYER ((RES*TILE*2 + CINC*TILE) * 4)   /* 106496 bytes */
#define SMEM_FINAL (RES*TILE*2 * 4)                 /* 65536 bytes  */

typedef unsigned long long u64;

// ---------------- device scratch (no allocations allowed) ----------------
__device__ float g_hA[BB*RES*TLEN];
__device__ float g_hB[BB*RES*TLEN];
__device__ float g_skip[BB*SKC*TLEN];
__device__ float g_c[BB*CINC*TLEN];
__device__ float g_cA[BB*CINC*400];
__device__ float g_cB[BB*CINC*4000];
__device__ float g_Wg[NL*208*GATE];
__device__ float g_Wz[NL*64*GATE];
__device__ int   g_xflag;   // 1 => x stored as int32, 0 => int64

// ---------------- packed f32x2 helpers ----------------
__device__ __forceinline__ void ffma2(u64& acc, u64 ab, u64 h2) {
    asm("fma.rn.f32x2 %0, %1, %2, %0;" : "+l"(acc) : "l"(ab), "l"(h2));
}
__device__ __forceinline__ u64 pack2(float x) {
    u64 r;
    asm("mov.b64 %0, {%1, %1};" : "=l"(r) : "f"(x));
    return r;
}
__device__ __forceinline__ float2 unpack2(u64 v) {
    float2 r;
    asm("mov.b64 {%0, %1}, %2;" : "=f"(r.x), "=f"(r.y) : "l"(v));
    return r;
}

// ---------------- helpers ----------------
__device__ __forceinline__ float sigf(float x) {
    return __fdividef(1.f, 1.f + __expf(-x));
}
__device__ __forceinline__ float tanhfast(float x) {
    return 2.f * sigf(2.f * x) - 1.f;
}

// ---------------- dtype detection for x ----------------
__global__ void k_detect(const unsigned* __restrict__ xu) {
    __shared__ int s_any;
    if (threadIdx.x == 0) s_any = 0;
    __syncthreads();
    int any = 0;
    for (int i = 1 + 2*threadIdx.x; i < BB*TLEN; i += 2*blockDim.x)
        any |= (xu[i] != 0u);
    if (any) atomicOr(&s_any, 1);
    __syncthreads();
    if (threadIdx.x == 0) g_xflag = s_any;
}

// ---------------- first 1x1 conv (one-hot gather) + skip reset ----------------
__global__ void k_first(const void* __restrict__ xraw,
                        const float* __restrict__ fw,
                        const float* __restrict__ fb) {
    int g = blockIdx.x * blockDim.x + threadIdx.x;
    if (g >= BB*TLEN) return;
    int t = g % TLEN, b = g / TLEN;
    int xi = g_xflag ? ((const int*)xraw)[g]
                     : (int)(((const long long*)xraw)[g]);
    #pragma unroll 4
    for (int o = 0; o < RES; ++o) {
        g_hA[(b*RES + o)*TLEN + t]  = fw[o*OUTC + xi] + fb[o];
        g_skip[(b*SKC + o)*TLEN + t] = 0.f;
    }
}

// ---------------- weight packing (k-major) ----------------
__global__ void k_prep(const float* __restrict__ conv_w,
                       const float* __restrict__ cond_w,
                       const float* __restrict__ skip_w,
                       const float* __restrict__ out_w) {
    int i = blockIdx.x * blockDim.x + threadIdx.x;
    const int NG = NL*208*GATE;
    if (i < NG) {
        int l = i / (208*GATE);
        int rem = i % (208*GATE);
        int r = rem / GATE, o = rem % GATE;
        float v;
        if (r < 64)        v = conv_w[((l*GATE + o)*RES + r)*2 + 0];
        else if (r < 128)  v = conv_w[((l*GATE + o)*RES + (r-64))*2 + 1];
        else               v = cond_w[(l*GATE + o)*CINC + (r-128)];
        g_Wg[i] = v;
    } else {
        int j = i - NG;
        if (j < NL*64*GATE) {
            int l = j / (64*GATE);
            int rem = j % (64*GATE);
            int k = rem / GATE, o = rem % GATE;
            g_Wz[j] = (o < 64) ? skip_w[(l*SKC + o)*64 + k]
                               : out_w[(l*RES + (o-64))*64 + k];
        }
    }
}

// ---------------- conditioning upsample ----------------
__global__ void k_upA(const float* __restrict__ cond,
                      const float* __restrict__ cin_w) {
    int i = blockIdx.x * blockDim.x + threadIdx.x;
    if (i >= BB*CINC*400) return;
    int f = i % 400, o = (i/400) % CINC, b = i / (CINC*400);
    const float* cp = cond + b*CINC*400 + f;
    const float* wp = cin_w + o*CINC;
    float s = 0.f;
    #pragma unroll 8
    for (int k = 0; k < CINC; ++k) s += wp[k] * cp[k*400];
    g_cA[i] = s;
}

__global__ void k_upB() {
    int i = blockIdx.x * blockDim.x + threadIdx.x;
    if (i >= BB*CINC*4000) return;
    int t = i % 4000, bc = i / 4000;
    int lo = (t-10 < 0) ? 0 : t-10;
    int hi = (t+10 > 3999) ? 3999 : t+10;
    const float* src = g_cA + bc*400;
    float s = 0.f;
    for (int j = lo; j <= hi; ++j) s += src[j/10];
    g_cB[i] = s * (1.f/21.f);
}

__global__ void k_upC() {
    int i = blockIdx.x * blockDim.x + threadIdx.x;
    if (i >= BB*CINC*TLEN) return;
    int t = i % TLEN, bc = i / TLEN;
    int lo = (t-8 < 0) ? 0 : t-8;
    int hi = (t+8 > TLEN-1) ? TLEN-1 : t+8;
    const float* src = g_cB + bc*4000;
    float s = 0.f;
    for (int j = lo; j <= hi; ++j) s += src[j >> 3];
    g_c[i] = s * (1.f/17.f);
}

// ---------------- per-layer fused kernel (packed f32x2) ----------------
// Per thread: 4 output channels x 8 timestep-PAIRS.
// Pair p = tg + 8*j covers timesteps t = 2p, 2p+1  (p in 0..63).
__device__ __forceinline__ void gemm_acc2(const float* __restrict__ W,
                                          const float* __restrict__ S,
                                          int rows, int og, int tg,
                                          u64 acc[4][8]) {
    #pragma unroll 4
    for (int r = 0; r < rows; ++r) {
        float4 w = *(const float4*)(W + r*GATE + og*4);
        u64 w0 = pack2(w.x), w1 = pack2(w.y), w2 = pack2(w.z), w3 = pack2(w.w);
        const u64* sv = (const u64*)(S + r*TILE) + tg;
        #pragma unroll
        for (int j = 0; j < 8; ++j) {
            u64 h2 = sv[j*8];
            ffma2(acc[0][j], w0, h2);
            ffma2(acc[1][j], w1, h2);
            ffma2(acc[2][j], w2, h2);
            ffma2(acc[3][j], w3, h2);
        }
    }
}

__global__ void __launch_bounds__(NTH, 2) k_layer(int l, int d,
        const float* __restrict__ conv_b,
        const float* __restrict__ skip_b,
        const float* __restrict__ out_b) {
    extern __shared__ float sm[];
    float* sh_hc = sm;                   // [64][128]
    float* sh_hp = sm + RES*TILE;        // [64][128]
    float* sh_c  = sm + 2*RES*TILE;      // [80][128]
    float* sh_g  = sm + RES*TILE;        // [128][128], overlaps hp+c after sync

    const float* hin  = (l & 1) ? g_hB : g_hA;
    float*       hout = (l & 1) ? g_hA : g_hB;

    int b  = blockIdx.y;
    int t0 = blockIdx.x * TILE;
    int tid = threadIdx.x;
    const float* hb = hin + b*RES*TLEN;

    // load h(t) tile (vectorized)
    for (int i = tid; i < RES*(TILE/4); i += NTH) {
        int r = i >> 5, c4 = i & 31;
        ((float4*)sh_hc)[i] = *(const float4*)(hb + r*TLEN + t0 + c4*4);
    }
    // load h(t-d) tile with zero pad
    for (int i = tid; i < RES*TILE; i += NTH) {
        int r = i >> 7, c = i & (TILE-1);
        int t = t0 - d + c;
        sh_hp[i] = (t >= 0) ? hb[r*TLEN + t] : 0.f;
    }
    // load c tile
    const float* cb = g_c + b*CINC*TLEN;
    for (int i = tid; i < CINC*(TILE/4); i += NTH) {
        int r = i >> 5, c4 = i & 31;
        ((float4*)sh_c)[i] = *(const float4*)(cb + r*TLEN + t0 + c4*4);
    }
    __syncthreads();

    int og = tid >> 3;   // 0..31 -> output channels og*4..og*4+3
    int tg = tid & 7;    // pair phase

    // --- stage 1: g = W0 @ h(t-d) + W1 @ h(t) + Wc @ c + bias ---
    u64 acc[4][8];
    #pragma unroll
    for (int i = 0; i < 4; ++i) {
        u64 bi = pack2(conv_b[og*4 + i]);
        #pragma unroll
        for (int j = 0; j < 8; ++j) acc[i][j] = bi;
    }
    const float* Wl = g_Wg + (size_t)l*208*GATE;
    gemm_acc2(Wl,            sh_hp, 64, og, tg, acc);
    gemm_acc2(Wl + 64*GATE,  sh_hc, 64, og, tg, acc);
    gemm_acc2(Wl + 128*GATE, sh_c,  80, og, tg, acc);
    __syncthreads();   // done reading hp/c; reuse region for g

    #pragma unroll
    for (int i = 0; i < 4; ++i)
        #pragma unroll
        for (int j = 0; j < 8; ++j)
            *(u64*)(sh_g + (og*4 + i)*TILE + 2*(tg + 8*j)) = acc[i][j];
    __syncthreads();

    // --- gate: z = tanh(a) * sigmoid(b), in place over rows 0..63 ---
    for (int i = tid; i < 64*TILE; i += NTH) {
        float a  = sh_g[i];
        float bq = sh_g[i + 64*TILE];
        sh_g[i] = tanhfast(a) * sigf(bq);
    }
    __syncthreads();

    // --- stage 2: [skip_w; out_w] @ z ---
    u64 acc2[4][8];
    {
        const float* bias = (og < 16) ? (skip_b + og*4) : (out_b + (og-16)*4);
        #pragma unroll
        for (int i = 0; i < 4; ++i) {
            u64 bi = pack2(bias[i]);
            #pragma unroll
            for (int j = 0; j < 8; ++j) acc2[i][j] = bi;
        }
    }
    gemm_acc2(g_Wz + (size_t)l*64*GATE, sh_g, 64, og, tg, acc2);

    if (og < 16) {
        float2* sp = (float2*)(g_skip + (b*SKC + og*4)*TLEN + t0);
        #pragma unroll
        for (int i = 0; i < 4; ++i) {
            float2* row = sp + i*(TLEN/2);
            #pragma unroll
            for (int j = 0; j < 8; ++j) {
                float2 v = row[tg + 8*j];
                float2 a = unpack2(acc2[i][j]);
                v.x += a.x; v.y += a.y;
                row[tg + 8*j] = v;
            }
        }
    } else {
        int oo = (og - 16) * 4;
        #pragma unroll
        for (int i = 0; i < 4; ++i) {
            float2* row = (float2*)(hout + (b*RES + oo + i)*TLEN + t0);
            const float2* hcv = (const float2*)(sh_hc + (oo + i)*TILE);
            #pragma unroll
            for (int j = 0; j < 8; ++j) {
                float2 hc = hcv[tg + 8*j];
                float2 a  = unpack2(acc2[i][j]);
                hc.x += a.x; hc.y += a.y;
                row[tg + 8*j] = hc;
            }
        }
    }
}

// ---------------- output head: relu -> 64x64 -> relu -> 256x64 ----------------
__global__ void __launch_bounds__(NTH) k_final(const float* __restrict__ w1,
                                               const float* __restrict__ b1,
                                               const float* __restrict__ w2,
                                               const float* __restrict__ b2,
                                               float* __restrict__ out) {
    extern __shared__ float sm[];
    float* sh_s = sm;              // relu(skips) [64][128]
    float* sh_y = sm + RES*TILE;   // relu(y1)    [64][128]
    int b = blockIdx.y, t0 = blockIdx.x * TILE, tid = threadIdx.x;

    for (int i = tid; i < RES*(TILE/4); i += NTH) {
        int r = i >> 5, c4 = i & 31;
        float4 v = *(const float4*)(g_skip + (b*SKC + r)*TLEN + t0 + c4*4);
        v.x = fmaxf(v.x, 0.f); v.y = fmaxf(v.y, 0.f);
        v.z = fmaxf(v.z, 0.f); v.w = fmaxf(v.w, 0.f);
        ((float4*)sh_s)[i] = v;
    }
    __syncthreads();

    int og = tid >> 3, tg = tid & 7;   // og 0..31

    // phase A: y1 = relu(w1 @ s + b1), 2 channels per thread
    {
        u64 a0[8], a1[8];
        u64 c0 = pack2(b1[og*2]), c1 = pack2(b1[og*2+1]);
        #pragma unroll
        for (int j = 0; j < 8; ++j) { a0[j] = c0; a1[j] = c1; }
        #pragma unroll 4
        for (int r = 0; r < 64; ++r) {
            u64 w0 = pack2(w1[(og*2+0)*64 + r]);
            u64 w1v = pack2(w1[(og*2+1)*64 + r]);
            const u64* sv = (const u64*)(sh_s + r*TILE) + tg;
            #pragma unroll
            for (int j = 0; j < 8; ++j) {
                u64 s = sv[j*8];
                ffma2(a0[j], w0, s);
                ffma2(a1[j], w1v, s);
            }
        }
        #pragma unroll
        for (int j = 0; j < 8; ++j) {
            float2 v0 = unpack2(a0[j]), v1 = unpack2(a1[j]);
            v0.x = fmaxf(v0.x, 0.f); v0.y = fmaxf(v0.y, 0.f);
            v1.x = fmaxf(v1.x, 0.f); v1.y = fmaxf(v1.y, 0.f);
            *(float2*)(sh_y + (og*2+0)*TILE + 2*(tg + 8*j)) = v0;
            *(float2*)(sh_y + (og*2+1)*TILE + 2*(tg + 8*j)) = v1;
        }
    }
    __syncthreads();

    // phase B: y = w2 @ y1 + b2, 256 channels in two passes of 4/thread
    #pragma unroll 1
    for (int p = 0; p < 2; ++p) {
        int ob = p*128 + og*4;
        u64 acc[4][8];
        #pragma unroll
        for (int i = 0; i < 4; ++i) {
            u64 bi = pack2(b2[ob + i]);
            #pragma unroll
            for (int j = 0; j < 8; ++j) acc[i][j] = bi;
        }
        #pragma unroll 4
        for (int r = 0; r < 64; ++r) {
            u64 w0 = pack2(w2[(ob+0)*64 + r]);
            u64 w1v = pack2(w2[(ob+1)*64 + r]);
            u64 w2v = pack2(w2[(ob+2)*64 + r]);
            u64 w3v = pack2(w2[(ob+3)*64 + r]);
            const u64* yv = (const u64*)(sh_y + r*TILE) + tg;
            #pragma unroll
            for (int j = 0; j < 8; ++j) {
                u64 y = yv[j*8];
                ffma2(acc[0][j], w0, y);
                ffma2(acc[1][j], w1v, y);
                ffma2(acc[2][j], w2v, y);
                ffma2(acc[3][j], w3v, y);
            }
        }
        #pragma unroll
        for (int i = 0; i < 4; ++i) {
            float2* row = (float2*)(out + ((size_t)b*OUTC + ob + i)*TLEN + t0);
            #pragma unroll
            for (int j = 0; j < 8; ++j)
                row[tg + 8*j] = unpack2(acc[i][j]);
        }
    }
}

// ---------------- launch ----------------
extern "C" void kernel_launch(void* const* d_in, const int* in_sizes, int n_in,
                              void* d_out, int out_size) {
    (void)in_sizes; (void)n_in; (void)out_size;
    const void*  x       = d_in[0];
    const float* cond    = (const float*)d_in[1];
    const float* first_w = (const float*)d_in[2];
    const float* first_b = (const float*)d_in[3];
    const float* cin_w   = (const float*)d_in[4];
    const float* conv_w  = (const float*)d_in[5];
    const float* conv_b  = (const float*)d_in[6];
    const float* cond_w  = (const float*)d_in[7];
    const float* skip_w  = (const float*)d_in[8];
    const float* skip_b  = (const float*)d_in[9];
    const float* out_w   = (const float*)d_in[10];
    const float* out_b   = (const float*)d_in[11];
    const float* l1w     = (const float*)d_in[12];
    const float* l1b     = (const float*)d_in[13];
    const float* l2w     = (const float*)d_in[14];
    const float* l2b     = (const float*)d_in[15];
    float* out = (float*)d_out;

    cudaFuncSetAttribute(k_layer, cudaFuncAttributeMaxDynamicSharedMemorySize, SMEM_LAYER);
    cudaFuncSetAttribute(k_final, cudaFuncAttributeMaxDynamicSharedMemorySize, SMEM_FINAL);

    k_detect<<<1, 256>>>((const unsigned*)x);
    k_first<<<(BB*TLEN + 255)/256, 256>>>(x, first_w, first_b);

    int nprep = NL*208*GATE + NL*64*GATE;
    k_prep<<<(nprep + 255)/256, 256>>>(conv_w, cond_w, skip_w, out_w);

    k_upA<<<(BB*CINC*400  + 255)/256, 256>>>(cond, cin_w);
    k_upB<<<(BB*CINC*4000 + 255)/256, 256>>>();
    k_upC<<<(BB*CINC*TLEN + 255)/256, 256>>>();

    dim3 grid(TLEN/TILE, BB);
    for (int l = 0; l < NL; ++l) {
        int d = 1 << (l % 10);
        k_layer<<<grid, NTH, SMEM_LAYER>>>(l, d,
            conv_b + l*GATE, skip_b + l*SKC, out_b + l*RES);
    }
    k_final<<<grid, NTH, SMEM_FINAL>>>(l1w, l1b, l2w, l2b, out);
}